// round 9
// baseline (speedup 1.0000x reference)
#include <cuda_runtime.h>
#include <math_constants.h>
#include <cstdint>

#define NNODES 65536
#define NEDGES 1048576
#define NGRAPH 64
#define NPER   1024
#define FEAT   64
#define HID    128
#define TOPK   10
#define ECAP   10240   // csr slab capacity per half-graph block (mean 8192, +32 sigma)

// ---------------- device scratch (no allocations allowed) ----------------
__device__ int    g_deg[NNODES];
__device__ float  g_dinv[NNODES];
__device__ int    g_off[NNODES];
__device__ int    g_cursor[NNODES];
__device__ int    g_bsum[256];
__device__ float2 g_csre[NEDGES];   // {bits(src_local), norm}
__device__ float  g_c[NNODES];
__device__ float  g_T0[NNODES * HID];
__device__ float  g_T1[NNODES * HID];
__device__ float  g_mpp[NGRAPH * 8 * HID];
__device__ float  g_gW[NGRAPH * HID];
__device__ float  g_z[NNODES];

// ---------------- tf32 helpers ----------------
__device__ __forceinline__ void split_tf32(float a, uint32_t& hi, uint32_t& lo) {
    asm("cvt.rna.tf32.f32 %0, %1;" : "=r"(hi) : "f"(a));
    float r = a - __uint_as_float(hi);
    asm("cvt.rna.tf32.f32 %0, %1;" : "=r"(lo) : "f"(r));
}

__device__ __forceinline__ void mma_tf32(float4& d, const uint32_t a[4], const uint32_t b[2]) {
    asm volatile(
        "mma.sync.aligned.m16n8k8.row.col.f32.tf32.tf32.f32 "
        "{%0,%1,%2,%3}, {%4,%5,%6,%7}, {%8,%9}, {%0,%1,%2,%3};"
        : "+f"(d.x), "+f"(d.y), "+f"(d.z), "+f"(d.w)
        : "r"(a[0]), "r"(a[1]), "r"(a[2]), "r"(a[3]), "r"(b[0]), "r"(b[1]));
}

// ---------------- CSR construction ----------------
__global__ void k_hist(const int* __restrict__ edst) {
    int e = blockIdx.x * 256 + threadIdx.x;
    if (e < NEDGES) atomicAdd(&g_deg[edst[e]], 1);
}

__global__ void k_scan1() {
    __shared__ int s[256];
    int t = threadIdx.x;
    int i = blockIdx.x * 256 + t;
    int v = g_deg[i];
    g_dinv[i] = rsqrtf((float)(v + 1));
    s[t] = v;
    __syncthreads();
    for (int off = 1; off < 256; off <<= 1) {
        int x = s[t];
        if (t >= off) x += s[t - off];
        __syncthreads();
        s[t] = x;
        __syncthreads();
    }
    g_off[i] = s[t] - v;
    if (t == 255) g_bsum[blockIdx.x] = s[t];
}

__global__ void k_scan2() {
    __shared__ int s[256];
    int t = threadIdx.x;
    int v = g_bsum[t];
    s[t] = v;
    __syncthreads();
    for (int off = 1; off < 256; off <<= 1) {
        int x = s[t];
        if (t >= off) x += s[t - off];
        __syncthreads();
        s[t] = x;
        __syncthreads();
    }
    g_bsum[t] = s[t] - v;   // exclusive
}

__global__ void k_scan3() {
    int i = blockIdx.x * 256 + threadIdx.x;
    int o = g_off[i] + g_bsum[blockIdx.x];
    g_off[i] = o;
    g_cursor[i] = o;
}

__global__ void k_fill(const int* __restrict__ esrc, const int* __restrict__ edst) {
    int e = blockIdx.x * 256 + threadIdx.x;
    if (e >= NEDGES) return;
    int s = esrc[e], d = edst[e];
    float nr = g_dinv[s] * g_dinv[d];
    int slot = atomicAdd(&g_cursor[d], 1);
    g_csre[slot] = make_float2(__int_as_float(s & (NPER - 1)), nr);
}

// ---------------- smem-resident aggregation (CSR slab + X slice both in smem) ------
// Block = half graph (512 dst nodes), 1024 threads. Slices of 32 features.
// smem: sE[ECAP] float2 (csr slab), sX[1024*32] (graph feature slice).
template <int K, bool WRITE_C>
__global__ __launch_bounds__(1024) void k_tagg(const float* __restrict__ X,
                                               float* __restrict__ Y) {
    extern __shared__ float sm[];
    float2* sE = (float2*)sm;            // ECAP entries
    float*  sX = sm + 2 * ECAP;          // 1024 x 32
    const int g = blockIdx.x >> 1, half = blockIdx.x & 1;
    const int base = g * NPER;
    const int nb = base + half * 512;
    const int tid = threadIdx.x;
    const int lane = tid & 31, w = tid >> 5;    // 32 warps

    const int off0 = g_off[nb];
    const int lastn = nb + 511;
    const int slab = g_off[lastn] + g_deg[lastn] - off0;
    const int ns = min(slab, ECAP);
    for (int i = tid; i < ns; i += 1024) sE[i] = g_csre[off0 + i];

    const int S = K / 32;
    for (int q = 0; q < S; q++) {
        __syncthreads();                 // covers sE on q=0, prior gather otherwise
        #pragma unroll 8
        for (int i = tid; i < 1024 * 8; i += 1024) {
            int row = i >> 3, c = (i & 7) * 4;
            *(float4*)&sX[row * 32 + c] =
                *(const float4*)&X[(size_t)(base + row) * K + q * 32 + c];
        }
        __syncthreads();
        for (int s = 0; s < 16; s++) {
            int ln = half * 512 + w + s * 32;        // graph-local dst node
            int node = base + ln;
            int jb = g_off[node] - off0;
            int dg = g_deg[node];
            float dv = g_dinv[node];
            float sl = dv * dv;
            float acc = sl * sX[ln * 32 + lane];
            float csum = sl;
            #pragma unroll 4
            for (int j = 0; j < dg; j++) {
                int lj = jb + j;
                float2 e = (lj < ECAP) ? sE[lj] : g_csre[off0 + lj];
                acc += e.y * sX[__float_as_int(e.x) * 32 + lane];
                if (WRITE_C) csum += e.y;
            }
            Y[(size_t)node * K + q * 32 + lane] = acc;
            if (WRITE_C && q == 0 && lane == 0) g_c[node] = csum;
        }
    }
}

// ---------------- 3xTF32 mma.sync GEMM: per-block 128 rows x 128 cols --------------
// MAXP: fold maxpool stage-1 into epilogue. ZOUT: skip Y store, emit z = h . W3.
template <int K, bool RELU, bool GLOB, bool MAXP, bool ZOUT>
__global__ __launch_bounds__(256) void k_mgemm(
    const float* __restrict__ A, const float* __restrict__ W,
    const float* __restrict__ bias, float* __restrict__ Y,
    const float* __restrict__ W3) {
    extern __shared__ float sm[];
    __shared__ int   smax[128];
    __shared__ float szp[128][8];
    const int PA = K + 4;
    float* sA = sm;                 // 128 * PA
    float* sB = sm + 128 * PA;      // K * 136
    const int tid = threadIdx.x;
    const int rbase = blockIdx.x * 128;

    if (MAXP && tid < 128) smax[tid] = 0;

    for (int i = tid; i < 128 * (K / 4); i += 256) {
        int row = i / (K / 4), c = i % (K / 4);
        float4 v = *(const float4*)&A[(size_t)(rbase + row) * K + c * 4];
        *(float4*)&sA[row * PA + c * 4] = v;
    }
    for (int i = tid; i < K * 32; i += 256) {
        int row = i / 32, c = i % 32;
        *(float4*)&sB[row * 136 + c * 4] = *(const float4*)&W[row * 128 + c * 4];
    }
    __syncthreads();

    const int lane = tid & 31, wid = tid >> 5;
    const int gp = lane >> 2, tg = lane & 3;
    const int m0 = (wid & 3) * 32, n0 = (wid >> 2) * 64;

    float4 acc[2][8];
    #pragma unroll
    for (int mf = 0; mf < 2; mf++)
        #pragma unroll
        for (int f = 0; f < 8; f++) acc[mf][f] = make_float4(0.f, 0.f, 0.f, 0.f);

    for (int ks = 0; ks < K / 8; ks++) {
        const int kc = ks * 8;
        uint32_t ah[2][4], al[2][4];
        #pragma unroll
        for (int mf = 0; mf < 2; mf++) {
            int r0 = m0 + mf * 16 + gp;
            float x0 = sA[r0 * PA + kc + tg];
            float x1 = sA[(r0 + 8) * PA + kc + tg];
            float x2 = sA[r0 * PA + kc + tg + 4];
            float x3 = sA[(r0 + 8) * PA + kc + tg + 4];
            split_tf32(x0, ah[mf][0], al[mf][0]);
            split_tf32(x1, ah[mf][1], al[mf][1]);
            split_tf32(x2, ah[mf][2], al[mf][2]);
            split_tf32(x3, ah[mf][3], al[mf][3]);
        }
        #pragma unroll
        for (int f = 0; f < 8; f++) {
            int n = n0 + f * 8 + gp;
            float y0 = sB[(kc + tg) * 136 + n];
            float y1 = sB[(kc + tg + 4) * 136 + n];
            uint32_t bh[2], bl[2];
            split_tf32(y0, bh[0], bl[0]);
            split_tf32(y1, bh[1], bl[1]);
            #pragma unroll
            for (int mf = 0; mf < 2; mf++) {
                mma_tf32(acc[mf][f], ah[mf], bh);
                mma_tf32(acc[mf][f], ah[mf], bl);
                mma_tf32(acc[mf][f], al[mf], bh);
            }
        }
    }

    float colmax[8][2];
    if (MAXP) {
        #pragma unroll
        for (int f = 0; f < 8; f++) { colmax[f][0] = 0.f; colmax[f][1] = 0.f; }
    }
    float zp[2][2] = {{0.f, 0.f}, {0.f, 0.f}};

    const float* gw = GLOB ? &g_gW[(rbase >> 10) * HID] : nullptr;
    #pragma unroll
    for (int mf = 0; mf < 2; mf++) {
        int r0 = rbase + m0 + mf * 16 + gp;
        int r1 = r0 + 8;
        float cc0 = GLOB ? g_c[r0] : 0.f;
        float cc1 = GLOB ? g_c[r1] : 0.f;
        #pragma unroll
        for (int f = 0; f < 8; f++) {
            int c = n0 + f * 8 + 2 * tg;
            float2 bv = *(const float2*)&bias[c];
            float4 a = acc[mf][f];
            float2 o0 = {a.x + bv.x, a.y + bv.y};
            float2 o1 = {a.z + bv.x, a.w + bv.y};
            if (GLOB) {
                float2 gv = *(const float2*)&gw[c];
                o0.x += cc0 * gv.x; o0.y += cc0 * gv.y;
                o1.x += cc1 * gv.x; o1.y += cc1 * gv.y;
            }
            if (RELU) {
                o0.x = fmaxf(o0.x, 0.f); o0.y = fmaxf(o0.y, 0.f);
                o1.x = fmaxf(o1.x, 0.f); o1.y = fmaxf(o1.y, 0.f);
            }
            if (!ZOUT) {
                *(float2*)&Y[(size_t)r0 * 128 + c] = o0;
                *(float2*)&Y[(size_t)r1 * 128 + c] = o1;
            }
            if (MAXP) {
                colmax[f][0] = fmaxf(colmax[f][0], fmaxf(o0.x, o1.x));
                colmax[f][1] = fmaxf(colmax[f][1], fmaxf(o0.y, o1.y));
            }
            if (ZOUT) {
                float w3a = W3[c], w3b = W3[c + 1];
                zp[mf][0] += o0.x * w3a + o0.y * w3b;
                zp[mf][1] += o1.x * w3a + o1.y * w3b;
            }
        }
    }

    if (MAXP) {
        #pragma unroll
        for (int f = 0; f < 8; f++) {
            int c = n0 + f * 8 + 2 * tg;
            atomicMax(&smax[c],     __float_as_int(colmax[f][0]));
            atomicMax(&smax[c + 1], __float_as_int(colmax[f][1]));
        }
        __syncthreads();
        if (tid < 128) g_mpp[(size_t)blockIdx.x * HID + tid] = __int_as_float(smax[tid]);
    }

    if (ZOUT) {
        int slot = ((wid >> 2) << 2) | tg;
        #pragma unroll
        for (int mf = 0; mf < 2; mf++) {
            szp[m0 + mf * 16 + gp][slot]     = zp[mf][0];
            szp[m0 + mf * 16 + gp + 8][slot] = zp[mf][1];
        }
        __syncthreads();
        if (tid < 128) {
            float z = 0.f;
            #pragma unroll
            for (int k = 0; k < 8; k++) z += szp[tid][k];
            g_z[rbase + tid] = z;
        }
    }
}

// ---------------- fused maxpool stage-2 + global path matmuls ----------------
__global__ void k_globs2(const float* __restrict__ Wf, const float* __restrict__ bf,
                         const float* __restrict__ W2) {
    __shared__ float s1[HID];
    __shared__ float s2[HID];
    int g = blockIdx.x, t = threadIdx.x;
    float m = -CUDART_INF_F;
    #pragma unroll
    for (int s = 0; s < 8; s++) m = fmaxf(m, g_mpp[(g * 8 + s) * HID + t]);
    s1[t] = m;
    __syncthreads();
    float acc = bf[t];
    for (int k = 0; k < HID; k++) acc += s1[k] * Wf[k * HID + t];
    s2[t] = acc;
    __syncthreads();
    float a2 = 0.f;
    for (int k = 0; k < HID; k++) a2 += s2[k] * W2[(HID + k) * HID + t];
    g_gW[g * HID + t] = a2;
}

// ---------------- fused logit + per-graph top-K mask (R5-proven) ----------------
__global__ __launch_bounds__(256) void k_logitk(const float* __restrict__ b3,
                                                float* __restrict__ out) {
    __shared__ float sz[NPER];
    __shared__ float slog[NPER];
    __shared__ float v[NPER];
    __shared__ float wmax[8];
    __shared__ float sth;
    __shared__ int sidx;
    const int g = blockIdx.x, t = threadIdx.x;
    const int lane = t & 31, warp = t >> 5;
    const float bb = b3[0];

    for (int i = t; i < NPER; i += 256) sz[i] = g_z[g * NPER + i];
    __syncthreads();

    for (int ln = warp; ln < NPER; ln += 8) {
        int node = g * NPER + ln;
        int jb = g_off[node], dg = g_deg[node];
        float part = 0.f;
        for (int j = lane; j < dg; j += 32) {
            float2 e = g_csre[jb + j];
            part += e.y * sz[__float_as_int(e.x)];
        }
        #pragma unroll
        for (int o = 16; o; o >>= 1) part += __shfl_xor_sync(0xffffffffu, part, o);
        if (lane == 0) {
            float dv = g_dinv[node];
            float lv = part + dv * dv * sz[ln] + bb;
            slog[ln] = lv;
            v[ln] = lv;
        }
    }
    __syncthreads();

    for (int it = 0; it < TOPK; it++) {
        float m = -CUDART_INF_F;
        for (int i = t; i < NPER; i += 256) m = fmaxf(m, v[i]);
        #pragma unroll
        for (int o = 16; o; o >>= 1) m = fmaxf(m, __shfl_xor_sync(0xffffffffu, m, o));
        if (lane == 0) wmax[warp] = m;
        __syncthreads();
        if (t == 0) {
            float mm = wmax[0];
            #pragma unroll
            for (int w = 1; w < 8; w++) mm = fmaxf(mm, wmax[w]);
            sth = mm;
            sidx = 0x7fffffff;
        }
        __syncthreads();
        float mm = sth;
        for (int i = t; i < NPER; i += 256)
            if (v[i] == mm) atomicMin(&sidx, i);
        __syncthreads();
        if (t == 0) v[sidx] = -CUDART_INF_F;
        __syncthreads();
    }
    float th = sth;
    for (int i = t; i < NPER; i += 256)
        out[g * NPER + i] = (slog[i] >= th) ? 1.0f : 0.0f;
}

// ---------------- host launcher ----------------
extern "C" void kernel_launch(void* const* d_in, const int* in_sizes, int n_in,
                              void* d_out, int out_size) {
    const float* x    = (const float*)d_in[0];
    const int*   esrc = (const int*)d_in[1];
    const int*   edst = (const int*)d_in[2];
    const float* W0 = (const float*)d_in[4];
    const float* b0 = (const float*)d_in[5];
    const float* W1 = (const float*)d_in[6];
    const float* b1 = (const float*)d_in[7];
    const float* Wf = (const float*)d_in[8];
    const float* bf = (const float*)d_in[9];
    const float* W2 = (const float*)d_in[10];
    const float* b2 = (const float*)d_in[11];
    const float* W3 = (const float*)d_in[12];
    const float* b3 = (const float*)d_in[13];
    float* out = (float*)d_out;

    float *T0, *T1;
    int* degp;
    cudaGetSymbolAddress((void**)&T0, g_T0);
    cudaGetSymbolAddress((void**)&T1, g_T1);
    cudaGetSymbolAddress((void**)&degp, g_deg);

    const int SMAGG = (2 * ECAP + 1024 * 32) * 4;    // 212992 (208 KB)
    const int SM64  = (128 * 68 + 64 * 136) * 4;     // 69632
    const int SM128 = (128 * 132 + 128 * 136) * 4;   // 137216
    cudaFuncSetAttribute(k_tagg<64, true>,   cudaFuncAttributeMaxDynamicSharedMemorySize, SMAGG);
    cudaFuncSetAttribute(k_tagg<128, false>, cudaFuncAttributeMaxDynamicSharedMemorySize, SMAGG);
    cudaFuncSetAttribute(k_mgemm<64, true, false, true, false>,
                         cudaFuncAttributeMaxDynamicSharedMemorySize, SM64);
    cudaFuncSetAttribute(k_mgemm<128, true, false, false, false>,
                         cudaFuncAttributeMaxDynamicSharedMemorySize, SM128);
    cudaFuncSetAttribute(k_mgemm<128, true, true, false, true>,
                         cudaFuncAttributeMaxDynamicSharedMemorySize, SM128);

    // --- CSR + norms ---
    cudaMemsetAsync(degp, 0, NNODES * sizeof(int));
    k_hist<<<NEDGES / 256, 256>>>(edst);
    k_scan1<<<256, 256>>>();
    k_scan2<<<1, 256>>>();
    k_scan3<<<256, 256>>>();
    k_fill<<<NEDGES / 256, 256>>>(esrc, edst);

    // --- conv0: h0 = relu(agg(x) @ W0 + b0); epilogue emits maxpool partials ---
    k_tagg<64, true><<<NGRAPH * 2, 1024, SMAGG>>>(x, T1);
    k_mgemm<64, true, false, true, false><<<NNODES / 128, 256, SM64>>>(T1, W0, b0, T0, nullptr);

    // --- global path: mp2 + (mp @ Wf + bf) @ W2_bottom ---
    k_globs2<<<NGRAPH, HID>>>(Wf, bf, W2);

    // --- conv1 (applied twice with same weights) ---
    k_tagg<128, false><<<NGRAPH * 2, 1024, SMAGG>>>(T0, T1);
    k_mgemm<128, true, false, false, false><<<NNODES / 128, 256, SM128>>>(T1, W1, b1, T0, nullptr);
    k_tagg<128, false><<<NGRAPH * 2, 1024, SMAGG>>>(T0, T1);
    k_mgemm<128, true, false, false, false><<<NNODES / 128, 256, SM128>>>(T1, W1, b1, T0, nullptr);

    // --- conv2 + conv3 projection fused: epilogue computes z = h . W3, no h store ---
    k_tagg<128, false><<<NGRAPH * 2, 1024, SMAGG>>>(T0, T1);
    k_mgemm<128, true, true, false, true><<<NNODES / 128, 256, SM128>>>(T1, W2, b2, nullptr, W3);

    // --- fused logit + per-graph top-10 mask ---
    k_logitk<<<NGRAPH, 256>>>(b3, out);
}

// round 10
// speedup vs baseline: 1.1764x; 1.1764x over previous
#include <cuda_runtime.h>
#include <math_constants.h>
#include <cstdint>

#define NNODES 65536
#define NEDGES 1048576
#define NGRAPH 64
#define NPER   1024
#define FEAT   64
#define HID    128
#define TOPK   10

// ---------------- device scratch (no allocations allowed) ----------------
__device__ int   g_deg[NNODES];
__device__ float g_dinv[NNODES];
__device__ int   g_off[NNODES];
__device__ int   g_cursor[NNODES];
__device__ int   g_bsum[256];
__device__ int   g_csrsrc[NEDGES];
__device__ float g_csrnrm[NEDGES];
__device__ float g_c[NNODES];
__device__ float g_T0[NNODES * HID];
__device__ float g_T1[NNODES * HID];
__device__ float g_mpp[NGRAPH * 8 * HID];
__device__ float g_gW[NGRAPH * HID];
__device__ float g_z[NNODES];

// ---------------- tf32 helpers ----------------
__device__ __forceinline__ void split_tf32(float a, uint32_t& hi, uint32_t& lo) {
    asm("cvt.rna.tf32.f32 %0, %1;" : "=r"(hi) : "f"(a));
    float r = a - __uint_as_float(hi);
    asm("cvt.rna.tf32.f32 %0, %1;" : "=r"(lo) : "f"(r));
}

__device__ __forceinline__ void mma_tf32(float4& d, const uint32_t a[4], const uint32_t b[2]) {
    asm volatile(
        "mma.sync.aligned.m16n8k8.row.col.f32.tf32.tf32.f32 "
        "{%0,%1,%2,%3}, {%4,%5,%6,%7}, {%8,%9}, {%0,%1,%2,%3};"
        : "+f"(d.x), "+f"(d.y), "+f"(d.z), "+f"(d.w)
        : "r"(a[0]), "r"(a[1]), "r"(a[2]), "r"(a[3]), "r"(b[0]), "r"(b[1]));
}

// ---------------- CSR construction ----------------
__global__ void k_hist(const int* __restrict__ edst) {
    int e = blockIdx.x * 256 + threadIdx.x;
    if (e < NEDGES) atomicAdd(&g_deg[edst[e]], 1);
}

__global__ void k_scan1() {
    __shared__ int s[256];
    int t = threadIdx.x;
    int i = blockIdx.x * 256 + t;
    int v = g_deg[i];
    g_dinv[i] = rsqrtf((float)(v + 1));
    s[t] = v;
    __syncthreads();
    for (int off = 1; off < 256; off <<= 1) {
        int x = s[t];
        if (t >= off) x += s[t - off];
        __syncthreads();
        s[t] = x;
        __syncthreads();
    }
    g_off[i] = s[t] - v;
    if (t == 255) g_bsum[blockIdx.x] = s[t];
}

__global__ void k_scan2() {
    __shared__ int s[256];
    int t = threadIdx.x;
    int v = g_bsum[t];
    s[t] = v;
    __syncthreads();
    for (int off = 1; off < 256; off <<= 1) {
        int x = s[t];
        if (t >= off) x += s[t - off];
        __syncthreads();
        s[t] = x;
        __syncthreads();
    }
    g_bsum[t] = s[t] - v;   // exclusive
}

__global__ void k_scan3() {
    int i = blockIdx.x * 256 + threadIdx.x;
    int o = g_off[i] + g_bsum[blockIdx.x];
    g_off[i] = o;
    g_cursor[i] = o;
}

__global__ void k_fill(const int* __restrict__ esrc, const int* __restrict__ edst) {
    int e = blockIdx.x * 256 + threadIdx.x;
    if (e >= NEDGES) return;
    int s = esrc[e], d = edst[e];
    float nr = g_dinv[s] * g_dinv[d];
    int slot = atomicAdd(&g_cursor[d], 1);
    g_csrsrc[slot] = s;
    g_csrnrm[slot] = nr;
}

// ---------------- sparse aggregations (warp per node, R3-proven loops) ----------
// WRITE_C: also emit c[n] = sum of incoming norms (replaces k_cvec).
template <bool WRITE_C>
__global__ __launch_bounds__(256) void k_agg64(const float* __restrict__ X,
                                               float* __restrict__ Y) {
    int node = blockIdx.x * 8 + (threadIdx.x >> 5);
    int lane = threadIdx.x & 31;
    const float2* xs = (const float2*)X;
    float dv = g_dinv[node];
    float2 xv = xs[node * 32 + lane];
    float2 acc;
    acc.x = dv * dv * xv.x;
    acc.y = dv * dv * xv.y;
    float csum = dv * dv;
    int jb = g_off[node], je = jb + g_deg[node];
    #pragma unroll 2
    for (int j = jb; j < je; j++) {
        int s = g_csrsrc[j];
        float nr = g_csrnrm[j];
        float2 v = xs[s * 32 + lane];
        acc.x += nr * v.x;
        acc.y += nr * v.y;
        if (WRITE_C) csum += nr;
    }
    ((float2*)Y)[node * 32 + lane] = acc;
    if (WRITE_C && lane == 0) g_c[node] = csum;
}

__global__ __launch_bounds__(256) void k_agg128(const float* __restrict__ X,
                                                float* __restrict__ Y) {
    int node = blockIdx.x * 8 + (threadIdx.x >> 5);
    int lane = threadIdx.x & 31;
    const float4* xs = (const float4*)X;
    float dv = g_dinv[node];
    float4 xv = xs[node * 32 + lane];
    float4 acc;
    float sl = dv * dv;
    acc.x = sl * xv.x; acc.y = sl * xv.y; acc.z = sl * xv.z; acc.w = sl * xv.w;
    int jb = g_off[node], je = jb + g_deg[node];
    #pragma unroll 2
    for (int j = jb; j < je; j++) {
        int s = g_csrsrc[j];
        float nr = g_csrnrm[j];
        float4 v = xs[s * 32 + lane];
        acc.x += nr * v.x; acc.y += nr * v.y; acc.z += nr * v.z; acc.w += nr * v.w;
    }
    ((float4*)Y)[node * 32 + lane] = acc;
}

// ---------------- 3xTF32 mma.sync GEMM: per-block 128 rows x 128 cols --------------
// MAXP: fold maxpool stage-1 into epilogue (block = one graph slice of 128 rows).
// ZOUT: skip Y store; instead compute z[row] = h_row . W3 (deterministic smem reduce).
template <int K, bool RELU, bool GLOB, bool MAXP, bool ZOUT>
__global__ __launch_bounds__(256) void k_mgemm(
    const float* __restrict__ A, const float* __restrict__ W,
    const float* __restrict__ bias, float* __restrict__ Y,
    const float* __restrict__ W3) {
    extern __shared__ float sm[];
    __shared__ int   smax[128];
    __shared__ float szp[128][8];
    const int PA = K + 4;
    float* sA = sm;                 // 128 * PA
    float* sB = sm + 128 * PA;      // K * 136
    const int tid = threadIdx.x;
    const int rbase = blockIdx.x * 128;

    if (MAXP && tid < 128) smax[tid] = 0;

    for (int i = tid; i < 128 * (K / 4); i += 256) {
        int row = i / (K / 4), c = i % (K / 4);
        float4 v = *(const float4*)&A[(size_t)(rbase + row) * K + c * 4];
        *(float4*)&sA[row * PA + c * 4] = v;
    }
    for (int i = tid; i < K * 32; i += 256) {
        int row = i / 32, c = i % 32;
        *(float4*)&sB[row * 136 + c * 4] = *(const float4*)&W[row * 128 + c * 4];
    }
    __syncthreads();

    const int lane = tid & 31, wid = tid >> 5;
    const int gp = lane >> 2, tg = lane & 3;
    const int m0 = (wid & 3) * 32, n0 = (wid >> 2) * 64;

    float4 acc[2][8];
    #pragma unroll
    for (int mf = 0; mf < 2; mf++)
        #pragma unroll
        for (int f = 0; f < 8; f++) acc[mf][f] = make_float4(0.f, 0.f, 0.f, 0.f);

    for (int ks = 0; ks < K / 8; ks++) {
        const int kc = ks * 8;
        uint32_t ah[2][4], al[2][4];
        #pragma unroll
        for (int mf = 0; mf < 2; mf++) {
            int r0 = m0 + mf * 16 + gp;
            float x0 = sA[r0 * PA + kc + tg];
            float x1 = sA[(r0 + 8) * PA + kc + tg];
            float x2 = sA[r0 * PA + kc + tg + 4];
            float x3 = sA[(r0 + 8) * PA + kc + tg + 4];
            split_tf32(x0, ah[mf][0], al[mf][0]);
            split_tf32(x1, ah[mf][1], al[mf][1]);
            split_tf32(x2, ah[mf][2], al[mf][2]);
            split_tf32(x3, ah[mf][3], al[mf][3]);
        }
        #pragma unroll
        for (int f = 0; f < 8; f++) {
            int n = n0 + f * 8 + gp;
            float y0 = sB[(kc + tg) * 136 + n];
            float y1 = sB[(kc + tg + 4) * 136 + n];
            uint32_t bh[2], bl[2];
            split_tf32(y0, bh[0], bl[0]);
            split_tf32(y1, bh[1], bl[1]);
            #pragma unroll
            for (int mf = 0; mf < 2; mf++) {
                mma_tf32(acc[mf][f], ah[mf], bh);
                mma_tf32(acc[mf][f], ah[mf], bl);
                mma_tf32(acc[mf][f], al[mf], bh);
            }
        }
    }

    float colmax[8][2];
    if (MAXP) {
        #pragma unroll
        for (int f = 0; f < 8; f++) { colmax[f][0] = 0.f; colmax[f][1] = 0.f; }
    }
    float zp[2][2] = {{0.f, 0.f}, {0.f, 0.f}};

    const float* gw = GLOB ? &g_gW[(rbase >> 10) * HID] : nullptr;
    #pragma unroll
    for (int mf = 0; mf < 2; mf++) {
        int r0 = rbase + m0 + mf * 16 + gp;
        int r1 = r0 + 8;
        float cc0 = GLOB ? g_c[r0] : 0.f;
        float cc1 = GLOB ? g_c[r1] : 0.f;
        #pragma unroll
        for (int f = 0; f < 8; f++) {
            int c = n0 + f * 8 + 2 * tg;
            float2 bv = *(const float2*)&bias[c];
            float4 a = acc[mf][f];
            float2 o0 = {a.x + bv.x, a.y + bv.y};
            float2 o1 = {a.z + bv.x, a.w + bv.y};
            if (GLOB) {
                float2 gv = *(const float2*)&gw[c];
                o0.x += cc0 * gv.x; o0.y += cc0 * gv.y;
                o1.x += cc1 * gv.x; o1.y += cc1 * gv.y;
            }
            if (RELU) {
                o0.x = fmaxf(o0.x, 0.f); o0.y = fmaxf(o0.y, 0.f);
                o1.x = fmaxf(o1.x, 0.f); o1.y = fmaxf(o1.y, 0.f);
            }
            if (!ZOUT) {
                *(float2*)&Y[(size_t)r0 * 128 + c] = o0;
                *(float2*)&Y[(size_t)r1 * 128 + c] = o1;
            }
            if (MAXP) {
                colmax[f][0] = fmaxf(colmax[f][0], fmaxf(o0.x, o1.x));
                colmax[f][1] = fmaxf(colmax[f][1], fmaxf(o0.y, o1.y));
            }
            if (ZOUT) {
                float w3a = W3[c], w3b = W3[c + 1];
                zp[mf][0] += o0.x * w3a + o0.y * w3b;
                zp[mf][1] += o1.x * w3a + o1.y * w3b;
            }
        }
    }

    if (MAXP) {
        #pragma unroll
        for (int f = 0; f < 8; f++) {
            int c = n0 + f * 8 + 2 * tg;
            atomicMax(&smax[c],     __float_as_int(colmax[f][0]));
            atomicMax(&smax[c + 1], __float_as_int(colmax[f][1]));
        }
        __syncthreads();
        if (tid < 128) g_mpp[(size_t)blockIdx.x * HID + tid] = __int_as_float(smax[tid]);
    }

    if (ZOUT) {
        int slot = ((wid >> 2) << 2) | tg;
        #pragma unroll
        for (int mf = 0; mf < 2; mf++) {
            szp[m0 + mf * 16 + gp][slot]     = zp[mf][0];
            szp[m0 + mf * 16 + gp + 8][slot] = zp[mf][1];
        }
        __syncthreads();
        if (tid < 128) {
            float z = 0.f;
            #pragma unroll
            for (int k = 0; k < 8; k++) z += szp[tid][k];
            g_z[rbase + tid] = z;
        }
    }
}

// ---------------- fused maxpool stage-2 + global path matmuls ----------------
__global__ void k_globs2(const float* __restrict__ Wf, const float* __restrict__ bf,
                         const float* __restrict__ W2) {
    __shared__ float s1[HID];
    __shared__ float s2[HID];
    int g = blockIdx.x, t = threadIdx.x;
    float m = -CUDART_INF_F;
    #pragma unroll
    for (int s = 0; s < 8; s++) m = fmaxf(m, g_mpp[(g * 8 + s) * HID + t]);
    s1[t] = m;
    __syncthreads();
    float acc = bf[t];
    for (int k = 0; k < HID; k++) acc += s1[k] * Wf[k * HID + t];
    s2[t] = acc;
    __syncthreads();
    float a2 = 0.f;
    for (int k = 0; k < HID; k++) a2 += s2[k] * W2[(HID + k) * HID + t];
    g_gW[g * HID + t] = a2;
}

// ---------------- fused logit + per-graph top-K mask ----------------
// z staged in smem; src indices are graph-local after masking (intra-graph edges).
__global__ __launch_bounds__(256) void k_logitk(const float* __restrict__ b3,
                                                float* __restrict__ out) {
    __shared__ float sz[NPER];
    __shared__ float slog[NPER];
    __shared__ float v[NPER];
    __shared__ float wmax[8];
    __shared__ float sth;
    __shared__ int sidx;
    const int g = blockIdx.x, t = threadIdx.x;
    const int lane = t & 31, warp = t >> 5;
    const float bb = b3[0];

    for (int i = t; i < NPER; i += 256) sz[i] = g_z[g * NPER + i];
    __syncthreads();

    for (int ln = warp; ln < NPER; ln += 8) {
        int node = g * NPER + ln;
        int jb = g_off[node], dg = g_deg[node];
        float part = 0.f;
        for (int j = lane; j < dg; j += 32)
            part += g_csrnrm[jb + j] * sz[g_csrsrc[jb + j] & (NPER - 1)];
        #pragma unroll
        for (int o = 16; o; o >>= 1) part += __shfl_xor_sync(0xffffffffu, part, o);
        if (lane == 0) {
            float dv = g_dinv[node];
            float lv = part + dv * dv * sz[ln] + bb;
            slog[ln] = lv;
            v[ln] = lv;
        }
    }
    __syncthreads();

    for (int it = 0; it < TOPK; it++) {
        float m = -CUDART_INF_F;
        for (int i = t; i < NPER; i += 256) m = fmaxf(m, v[i]);
        #pragma unroll
        for (int o = 16; o; o >>= 1) m = fmaxf(m, __shfl_xor_sync(0xffffffffu, m, o));
        if (lane == 0) wmax[warp] = m;
        __syncthreads();
        if (t == 0) {
            float mm = wmax[0];
            #pragma unroll
            for (int w = 1; w < 8; w++) mm = fmaxf(mm, wmax[w]);
            sth = mm;
            sidx = 0x7fffffff;
        }
        __syncthreads();
        float mm = sth;
        for (int i = t; i < NPER; i += 256)
            if (v[i] == mm) atomicMin(&sidx, i);
        __syncthreads();
        if (t == 0) v[sidx] = -CUDART_INF_F;
        __syncthreads();
    }
    float th = sth;
    for (int i = t; i < NPER; i += 256)
        out[g * NPER + i] = (slog[i] >= th) ? 1.0f : 0.0f;
}

// ---------------- host launcher ----------------
extern "C" void kernel_launch(void* const* d_in, const int* in_sizes, int n_in,
                              void* d_out, int out_size) {
    const float* x    = (const float*)d_in[0];
    const int*   esrc = (const int*)d_in[1];
    const int*   edst = (const int*)d_in[2];
    const float* W0 = (const float*)d_in[4];
    const float* b0 = (const float*)d_in[5];
    const float* W1 = (const float*)d_in[6];
    const float* b1 = (const float*)d_in[7];
    const float* Wf = (const float*)d_in[8];
    const float* bf = (const float*)d_in[9];
    const float* W2 = (const float*)d_in[10];
    const float* b2 = (const float*)d_in[11];
    const float* W3 = (const float*)d_in[12];
    const float* b3 = (const float*)d_in[13];
    float* out = (float*)d_out;

    float *T0, *T1;
    int* degp;
    cudaGetSymbolAddress((void**)&T0, g_T0);
    cudaGetSymbolAddress((void**)&T1, g_T1);
    cudaGetSymbolAddress((void**)&degp, g_deg);

    const int SM64  = (128 * 68 + 64 * 136) * 4;     // 69632
    const int SM128 = (128 * 132 + 128 * 136) * 4;   // 137216
    cudaFuncSetAttribute(k_mgemm<64, true, false, true, false>,
                         cudaFuncAttributeMaxDynamicSharedMemorySize, SM64);
    cudaFuncSetAttribute(k_mgemm<128, true, false, false, false>,
                         cudaFuncAttributeMaxDynamicSharedMemorySize, SM128);
    cudaFuncSetAttribute(k_mgemm<128, true, true, false, true>,
                         cudaFuncAttributeMaxDynamicSharedMemorySize, SM128);

    // --- CSR + norms ---
    cudaMemsetAsync(degp, 0, NNODES * sizeof(int));
    k_hist<<<NEDGES / 256, 256>>>(edst);
    k_scan1<<<256, 256>>>();
    k_scan2<<<1, 256>>>();
    k_scan3<<<256, 256>>>();
    k_fill<<<NEDGES / 256, 256>>>(esrc, edst);

    // --- conv0: h0 = relu(agg(x) @ W0 + b0); epilogue emits maxpool partials ---
    k_agg64<true><<<NNODES / 8, 256>>>(x, T1);
    k_mgemm<64, true, false, true, false><<<NNODES / 128, 256, SM64>>>(T1, W0, b0, T0, nullptr);

    // --- global path: mp2 + (mp @ Wf + bf) @ W2_bottom ---
    k_globs2<<<NGRAPH, HID>>>(Wf, bf, W2);

    // --- conv1 (applied twice with same weights) ---
    k_agg128<<<NNODES / 8, 256>>>(T0, T1);
    k_mgemm<128, true, false, false, false><<<NNODES / 128, 256, SM128>>>(T1, W1, b1, T0, nullptr);
    k_agg128<<<NNODES / 8, 256>>>(T0, T1);
    k_mgemm<128, true, false, false, false><<<NNODES / 128, 256, SM128>>>(T1, W1, b1, T0, nullptr);

    // --- conv2 + conv3 projection fused: epilogue computes z = h . W3, no h store ---
    k_agg128<<<NNODES / 8, 256>>>(T0, T1);
    k_mgemm<128, true, true, false, true><<<NNODES / 128, 256, SM128>>>(T1, W2, b2, nullptr, W3);

    // --- fused logit + per-graph top-10 mask ---
    k_logitk<<<NGRAPH, 256>>>(b3, out);
}

// round 11
// speedup vs baseline: 1.1831x; 1.0057x over previous
#include <cuda_runtime.h>
#include <math_constants.h>
#include <cstdint>

#define NNODES 65536
#define NEDGES 1048576
#define NGRAPH 64
#define NPER   1024
#define FEAT   64
#define HID    128
#define TOPK   10
#define EPG    16384   // edges per graph (exact: NPER * DEG)

// ---------------- device scratch (no allocations allowed) ----------------
__device__ int   g_deg[NNODES];
__device__ float g_dinv[NNODES];
__device__ int   g_off[NNODES];
__device__ int   g_cursor[NNODES];
__device__ int   g_csrsrc[NEDGES];
__device__ float g_csrnrm[NEDGES];
__device__ float g_c[NNODES];
__device__ float g_T0[NNODES * HID];
__device__ float g_T1[NNODES * HID];
__device__ float g_mpp[NGRAPH * 8 * HID];
__device__ float g_gW[NGRAPH * HID];
__device__ float g_z[NNODES];

// ---------------- tf32 helpers ----------------
__device__ __forceinline__ void split_tf32(float a, uint32_t& hi, uint32_t& lo) {
    asm("cvt.rna.tf32.f32 %0, %1;" : "=r"(hi) : "f"(a));
    float r = a - __uint_as_float(hi);
    asm("cvt.rna.tf32.f32 %0, %1;" : "=r"(lo) : "f"(r));
}

__device__ __forceinline__ void mma_tf32(float4& d, const uint32_t a[4], const uint32_t b[2]) {
    asm volatile(
        "mma.sync.aligned.m16n8k8.row.col.f32.tf32.tf32.f32 "
        "{%0,%1,%2,%3}, {%4,%5,%6,%7}, {%8,%9}, {%0,%1,%2,%3};"
        : "+f"(d.x), "+f"(d.y), "+f"(d.z), "+f"(d.w)
        : "r"(a[0]), "r"(a[1]), "r"(a[2]), "r"(a[3]), "r"(b[0]), "r"(b[1]));
}

// ---------------- CSR construction ----------------
__global__ void k_hist(const int* __restrict__ edst) {
    int e = blockIdx.x * 256 + threadIdx.x;
    if (e < NEDGES) atomicAdd(&g_deg[edst[e]], 1);
}

// per-graph scan: block = graph (1024 threads). Cross-graph base is the exact
// constant g*EPG (each graph owns exactly EPG edges). Fuses dinv.
__global__ __launch_bounds__(1024) void k_scan() {
    __shared__ int wsum[32];
    const int g = blockIdx.x, t = threadIdx.x;
    const int lane = t & 31, w = t >> 5;
    const int i = g * NPER + t;
    const int v = g_deg[i];
    g_dinv[i] = rsqrtf((float)(v + 1));
    int x = v;                         // inclusive warp scan
    #pragma unroll
    for (int o = 1; o < 32; o <<= 1) {
        int y = __shfl_up_sync(0xffffffffu, x, o);
        if (lane >= o) x += y;
    }
    if (lane == 31) wsum[w] = x;
    __syncthreads();
    if (w == 0) {
        int s = wsum[lane];
        #pragma unroll
        for (int o = 1; o < 32; o <<= 1) {
            int y = __shfl_up_sync(0xffffffffu, s, o);
            if (lane >= o) s += y;
        }
        wsum[lane] = s;
    }
    __syncthreads();
    int off = g * EPG + (w ? wsum[w - 1] : 0) + x - v;   // exclusive
    g_off[i] = off;
    g_cursor[i] = off;
}

__global__ void k_fill(const int* __restrict__ esrc, const int* __restrict__ edst) {
    int e = blockIdx.x * 256 + threadIdx.x;
    if (e >= NEDGES) return;
    int s = esrc[e], d = edst[e];
    float nr = g_dinv[s] * g_dinv[d];
    int slot = atomicAdd(&g_cursor[d], 1);
    g_csrsrc[slot] = s;
    g_csrnrm[slot] = nr;
}

// ---------------- sparse aggregations (warp per node, R3-proven loops) ----------
// WRITE_C: also emit c[n] = sum of incoming norms (replaces k_cvec).
template <bool WRITE_C>
__global__ __launch_bounds__(256) void k_agg64(const float* __restrict__ X,
                                               float* __restrict__ Y) {
    int node = blockIdx.x * 8 + (threadIdx.x >> 5);
    int lane = threadIdx.x & 31;
    const float2* xs = (const float2*)X;
    float dv = g_dinv[node];
    float2 xv = xs[node * 32 + lane];
    float2 acc;
    acc.x = dv * dv * xv.x;
    acc.y = dv * dv * xv.y;
    float csum = dv * dv;
    int jb = g_off[node], je = jb + g_deg[node];
    #pragma unroll 2
    for (int j = jb; j < je; j++) {
        int s = g_csrsrc[j];
        float nr = g_csrnrm[j];
        float2 v = xs[s * 32 + lane];
        acc.x += nr * v.x;
        acc.y += nr * v.y;
        if (WRITE_C) csum += nr;
    }
    ((float2*)Y)[node * 32 + lane] = acc;
    if (WRITE_C && lane == 0) g_c[node] = csum;
}

__global__ __launch_bounds__(256) void k_agg128(const float* __restrict__ X,
                                                float* __restrict__ Y) {
    int node = blockIdx.x * 8 + (threadIdx.x >> 5);
    int lane = threadIdx.x & 31;
    const float4* xs = (const float4*)X;
    float dv = g_dinv[node];
    float4 xv = xs[node * 32 + lane];
    float4 acc;
    float sl = dv * dv;
    acc.x = sl * xv.x; acc.y = sl * xv.y; acc.z = sl * xv.z; acc.w = sl * xv.w;
    int jb = g_off[node], je = jb + g_deg[node];
    #pragma unroll 2
    for (int j = jb; j < je; j++) {
        int s = g_csrsrc[j];
        float nr = g_csrnrm[j];
        float4 v = xs[s * 32 + lane];
        acc.x += nr * v.x; acc.y += nr * v.y; acc.z += nr * v.z; acc.w += nr * v.w;
    }
    ((float4*)Y)[node * 32 + lane] = acc;
}

// ---------------- 3xTF32 mma.sync GEMM: per-block 128 rows x 128 cols --------------
// MAXP: fold maxpool stage-1 into epilogue (block = one graph slice of 128 rows).
// ZOUT: skip Y store; instead compute z[row] = h_row . W3 (deterministic smem reduce).
template <int K, bool RELU, bool GLOB, bool MAXP, bool ZOUT>
__global__ __launch_bounds__(256) void k_mgemm(
    const float* __restrict__ A, const float* __restrict__ W,
    const float* __restrict__ bias, float* __restrict__ Y,
    const float* __restrict__ W3) {
    extern __shared__ float sm[];
    __shared__ int   smax[128];
    __shared__ float szp[128][8];
    const int PA = K + 4;
    float* sA = sm;                 // 128 * PA
    float* sB = sm + 128 * PA;      // K * 136
    const int tid = threadIdx.x;
    const int rbase = blockIdx.x * 128;

    if (MAXP && tid < 128) smax[tid] = 0;

    for (int i = tid; i < 128 * (K / 4); i += 256) {
        int row = i / (K / 4), c = i % (K / 4);
        float4 v = *(const float4*)&A[(size_t)(rbase + row) * K + c * 4];
        *(float4*)&sA[row * PA + c * 4] = v;
    }
    for (int i = tid; i < K * 32; i += 256) {
        int row = i / 32, c = i % 32;
        *(float4*)&sB[row * 136 + c * 4] = *(const float4*)&W[row * 128 + c * 4];
    }
    __syncthreads();

    const int lane = tid & 31, wid = tid >> 5;
    const int gp = lane >> 2, tg = lane & 3;
    const int m0 = (wid & 3) * 32, n0 = (wid >> 2) * 64;

    float4 acc[2][8];
    #pragma unroll
    for (int mf = 0; mf < 2; mf++)
        #pragma unroll
        for (int f = 0; f < 8; f++) acc[mf][f] = make_float4(0.f, 0.f, 0.f, 0.f);

    for (int ks = 0; ks < K / 8; ks++) {
        const int kc = ks * 8;
        uint32_t ah[2][4], al[2][4];
        #pragma unroll
        for (int mf = 0; mf < 2; mf++) {
            int r0 = m0 + mf * 16 + gp;
            float x0 = sA[r0 * PA + kc + tg];
            float x1 = sA[(r0 + 8) * PA + kc + tg];
            float x2 = sA[r0 * PA + kc + tg + 4];
            float x3 = sA[(r0 + 8) * PA + kc + tg + 4];
            split_tf32(x0, ah[mf][0], al[mf][0]);
            split_tf32(x1, ah[mf][1], al[mf][1]);
            split_tf32(x2, ah[mf][2], al[mf][2]);
            split_tf32(x3, ah[mf][3], al[mf][3]);
        }
        #pragma unroll
        for (int f = 0; f < 8; f++) {
            int n = n0 + f * 8 + gp;
            float y0 = sB[(kc + tg) * 136 + n];
            float y1 = sB[(kc + tg + 4) * 136 + n];
            uint32_t bh[2], bl[2];
            split_tf32(y0, bh[0], bl[0]);
            split_tf32(y1, bh[1], bl[1]);
            #pragma unroll
            for (int mf = 0; mf < 2; mf++) {
                mma_tf32(acc[mf][f], ah[mf], bh);
                mma_tf32(acc[mf][f], ah[mf], bl);
                mma_tf32(acc[mf][f], al[mf], bh);
            }
        }
    }

    float colmax[8][2];
    if (MAXP) {
        #pragma unroll
        for (int f = 0; f < 8; f++) { colmax[f][0] = 0.f; colmax[f][1] = 0.f; }
    }
    float zp[2][2] = {{0.f, 0.f}, {0.f, 0.f}};

    const float* gw = GLOB ? &g_gW[(rbase >> 10) * HID] : nullptr;
    #pragma unroll
    for (int mf = 0; mf < 2; mf++) {
        int r0 = rbase + m0 + mf * 16 + gp;
        int r1 = r0 + 8;
        float cc0 = GLOB ? g_c[r0] : 0.f;
        float cc1 = GLOB ? g_c[r1] : 0.f;
        #pragma unroll
        for (int f = 0; f < 8; f++) {
            int c = n0 + f * 8 + 2 * tg;
            float2 bv = *(const float2*)&bias[c];
            float4 a = acc[mf][f];
            float2 o0 = {a.x + bv.x, a.y + bv.y};
            float2 o1 = {a.z + bv.x, a.w + bv.y};
            if (GLOB) {
                float2 gv = *(const float2*)&gw[c];
                o0.x += cc0 * gv.x; o0.y += cc0 * gv.y;
                o1.x += cc1 * gv.x; o1.y += cc1 * gv.y;
            }
            if (RELU) {
                o0.x = fmaxf(o0.x, 0.f); o0.y = fmaxf(o0.y, 0.f);
                o1.x = fmaxf(o1.x, 0.f); o1.y = fmaxf(o1.y, 0.f);
            }
            if (!ZOUT) {
                *(float2*)&Y[(size_t)r0 * 128 + c] = o0;
                *(float2*)&Y[(size_t)r1 * 128 + c] = o1;
            }
            if (MAXP) {
                colmax[f][0] = fmaxf(colmax[f][0], fmaxf(o0.x, o1.x));
                colmax[f][1] = fmaxf(colmax[f][1], fmaxf(o0.y, o1.y));
            }
            if (ZOUT) {
                float w3a = W3[c], w3b = W3[c + 1];
                zp[mf][0] += o0.x * w3a + o0.y * w3b;
                zp[mf][1] += o1.x * w3a + o1.y * w3b;
            }
        }
    }

    if (MAXP) {
        #pragma unroll
        for (int f = 0; f < 8; f++) {
            int c = n0 + f * 8 + 2 * tg;
            atomicMax(&smax[c],     __float_as_int(colmax[f][0]));
            atomicMax(&smax[c + 1], __float_as_int(colmax[f][1]));
        }
        __syncthreads();
        if (tid < 128) g_mpp[(size_t)blockIdx.x * HID + tid] = __int_as_float(smax[tid]);
    }

    if (ZOUT) {
        int slot = ((wid >> 2) << 2) | tg;
        #pragma unroll
        for (int mf = 0; mf < 2; mf++) {
            szp[m0 + mf * 16 + gp][slot]     = zp[mf][0];
            szp[m0 + mf * 16 + gp + 8][slot] = zp[mf][1];
        }
        __syncthreads();
        if (tid < 128) {
            float z = 0.f;
            #pragma unroll
            for (int k = 0; k < 8; k++) z += szp[tid][k];
            g_z[rbase + tid] = z;
        }
    }
}

// ---------------- fused maxpool stage-2 + global path matmuls ----------------
__global__ void k_globs2(const float* __restrict__ Wf, const float* __restrict__ bf,
                         const float* __restrict__ W2) {
    __shared__ float s1[HID];
    __shared__ float s2[HID];
    int g = blockIdx.x, t = threadIdx.x;
    float m = -CUDART_INF_F;
    #pragma unroll
    for (int s = 0; s < 8; s++) m = fmaxf(m, g_mpp[(g * 8 + s) * HID + t]);
    s1[t] = m;
    __syncthreads();
    float acc = bf[t];
    for (int k = 0; k < HID; k++) acc += s1[k] * Wf[k * HID + t];
    s2[t] = acc;
    __syncthreads();
    float a2 = 0.f;
    for (int k = 0; k < HID; k++) a2 += s2[k] * W2[(HID + k) * HID + t];
    g_gW[g * HID + t] = a2;
}

// ---------------- fused logit + per-graph top-K mask ----------------
// z staged in smem; src indices masked to graph-local (edges are intra-graph).
__global__ __launch_bounds__(256) void k_logitk(const float* __restrict__ b3,
                                                float* __restrict__ out) {
    __shared__ float sz[NPER];
    __shared__ float slog[NPER];
    __shared__ float v[NPER];
    __shared__ float wmax[8];
    __shared__ float sth;
    __shared__ int sidx;
    const int g = blockIdx.x, t = threadIdx.x;
    const int lane = t & 31, warp = t >> 5;
    const float bb = b3[0];

    for (int i = t; i < NPER; i += 256) sz[i] = g_z[g * NPER + i];
    __syncthreads();

    for (int ln = warp; ln < NPER; ln += 8) {
        int node = g * NPER + ln;
        int jb = g_off[node], dg = g_deg[node];
        float part = 0.f;
        for (int j = lane; j < dg; j += 32)
            part += g_csrnrm[jb + j] * sz[g_csrsrc[jb + j] & (NPER - 1)];
        #pragma unroll
        for (int o = 16; o; o >>= 1) part += __shfl_xor_sync(0xffffffffu, part, o);
        if (lane == 0) {
            float dv = g_dinv[node];
            float lv = part + dv * dv * sz[ln] + bb;
            slog[ln] = lv;
            v[ln] = lv;
        }
    }
    __syncthreads();

    for (int it = 0; it < TOPK; it++) {
        float m = -CUDART_INF_F;
        for (int i = t; i < NPER; i += 256) m = fmaxf(m, v[i]);
        #pragma unroll
        for (int o = 16; o; o >>= 1) m = fmaxf(m, __shfl_xor_sync(0xffffffffu, m, o));
        if (lane == 0) wmax[warp] = m;
        __syncthreads();
        if (t == 0) {
            float mm = wmax[0];
            #pragma unroll
            for (int w = 1; w < 8; w++) mm = fmaxf(mm, wmax[w]);
            sth = mm;
            sidx = 0x7fffffff;
        }
        __syncthreads();
        float mm = sth;
        for (int i = t; i < NPER; i += 256)
            if (v[i] == mm) atomicMin(&sidx, i);
        __syncthreads();
        if (t == 0) v[sidx] = -CUDART_INF_F;
        __syncthreads();
    }
    float th = sth;
    for (int i = t; i < NPER; i += 256)
        out[g * NPER + i] = (slog[i] >= th) ? 1.0f : 0.0f;
}

// ---------------- host launcher ----------------
extern "C" void kernel_launch(void* const* d_in, const int* in_sizes, int n_in,
                              void* d_out, int out_size) {
    const float* x    = (const float*)d_in[0];
    const int*   esrc = (const int*)d_in[1];
    const int*   edst = (const int*)d_in[2];
    const float* W0 = (const float*)d_in[4];
    const float* b0 = (const float*)d_in[5];
    const float* W1 = (const float*)d_in[6];
    const float* b1 = (const float*)d_in[7];
    const float* Wf = (const float*)d_in[8];
    const float* bf = (const float*)d_in[9];
    const float* W2 = (const float*)d_in[10];
    const float* b2 = (const float*)d_in[11];
    const float* W3 = (const float*)d_in[12];
    const float* b3 = (const float*)d_in[13];
    float* out = (float*)d_out;

    float *T0, *T1;
    int* degp;
    cudaGetSymbolAddress((void**)&T0, g_T0);
    cudaGetSymbolAddress((void**)&T1, g_T1);
    cudaGetSymbolAddress((void**)&degp, g_deg);

    const int SM64  = (128 * 68 + 64 * 136) * 4;     // 69632
    const int SM128 = (128 * 132 + 128 * 136) * 4;   // 137216
    cudaFuncSetAttribute(k_mgemm<64, true, false, true, false>,
                         cudaFuncAttributeMaxDynamicSharedMemorySize, SM64);
    cudaFuncSetAttribute(k_mgemm<128, true, false, false, false>,
                         cudaFuncAttributeMaxDynamicSharedMemorySize, SM128);
    cudaFuncSetAttribute(k_mgemm<128, true, true, false, true>,
                         cudaFuncAttributeMaxDynamicSharedMemorySize, SM128);

    // --- CSR + norms (hist -> fused per-graph scan -> fill) ---
    cudaMemsetAsync(degp, 0, NNODES * sizeof(int));
    k_hist<<<NEDGES / 256, 256>>>(edst);
    k_scan<<<NGRAPH, 1024>>>();
    k_fill<<<NEDGES / 256, 256>>>(esrc, edst);

    // --- conv0: h0 = relu(agg(x) @ W0 + b0); epilogue emits maxpool partials ---
    k_agg64<true><<<NNODES / 8, 256>>>(x, T1);
    k_mgemm<64, true, false, true, false><<<NNODES / 128, 256, SM64>>>(T1, W0, b0, T0, nullptr);

    // --- global path: mp2 + (mp @ Wf + bf) @ W2_bottom ---
    k_globs2<<<NGRAPH, HID>>>(Wf, bf, W2);

    // --- conv1 (applied twice with same weights) ---
    k_agg128<<<NNODES / 8, 256>>>(T0, T1);
    k_mgemm<128, true, false, false, false><<<NNODES / 128, 256, SM128>>>(T1, W1, b1, T0, nullptr);
    k_agg128<<<NNODES / 8, 256>>>(T0, T1);
    k_mgemm<128, true, false, false, false><<<NNODES / 128, 256, SM128>>>(T1, W1, b1, T0, nullptr);

    // --- conv2 + conv3 projection fused: epilogue computes z = h . W3, no h store ---
    k_agg128<<<NNODES / 8, 256>>>(T0, T1);
    k_mgemm<128, true, true, false, true><<<NNODES / 128, 256, SM128>>>(T1, W2, b2, nullptr, W3);

    // --- fused logit + per-graph top-10 mask ---
    k_logitk<<<NGRAPH, 256>>>(b3, out);
}

// round 12
// speedup vs baseline: 1.2309x; 1.0404x over previous
#include <cuda_runtime.h>
#include <math_constants.h>
#include <cstdint>

#define NNODES 65536
#define NEDGES 1048576
#define NGRAPH 64
#define NPER   1024
#define FEAT   64
#define HID    128
#define TOPK   10
#define EPG    16384   // edges per graph (exact: NPER * DEG)

// ---------------- device scratch (no allocations allowed) ----------------
__device__ int   g_deg[NNODES];
__device__ float g_dinv[NNODES];
__device__ int   g_off[NNODES];
__device__ int   g_cursor[NNODES];
__device__ int   g_csrsrc[NEDGES];
__device__ float g_csrnrm[NEDGES];
__device__ float g_c[NNODES];
__device__ float g_T0[NNODES * HID];
__device__ float g_T1[NNODES * HID];
__device__ float g_mpp[NGRAPH * 8 * HID];
__device__ float g_gW[NGRAPH * HID];
__device__ float g_z[NNODES];

// ---------------- tf32 helpers ----------------
__device__ __forceinline__ void split_tf32(float a, uint32_t& hi, uint32_t& lo) {
    asm("cvt.rna.tf32.f32 %0, %1;" : "=r"(hi) : "f"(a));
    float r = a - __uint_as_float(hi);
    asm("cvt.rna.tf32.f32 %0, %1;" : "=r"(lo) : "f"(r));
}

__device__ __forceinline__ void mma_tf32(float4& d, const uint32_t a[4], const uint32_t b[2]) {
    asm volatile(
        "mma.sync.aligned.m16n8k8.row.col.f32.tf32.tf32.f32 "
        "{%0,%1,%2,%3}, {%4,%5,%6,%7}, {%8,%9}, {%0,%1,%2,%3};"
        : "+f"(d.x), "+f"(d.y), "+f"(d.z), "+f"(d.w)
        : "r"(a[0]), "r"(a[1]), "r"(a[2]), "r"(a[3]), "r"(b[0]), "r"(b[1]));
}

// ---------------- CSR construction ----------------
__global__ void k_hist(const int* __restrict__ edst) {
    int e = blockIdx.x * 256 + threadIdx.x;
    if (e < NEDGES) atomicAdd(&g_deg[edst[e]], 1);
}

// per-graph scan: block = graph (1024 threads). Cross-graph base is the exact
// constant g*EPG (each graph owns exactly EPG edges). Fuses dinv.
__global__ __launch_bounds__(1024) void k_scan() {
    __shared__ int wsum[32];
    const int g = blockIdx.x, t = threadIdx.x;
    const int lane = t & 31, w = t >> 5;
    const int i = g * NPER + t;
    const int v = g_deg[i];
    g_dinv[i] = rsqrtf((float)(v + 1));
    int x = v;                         // inclusive warp scan
    #pragma unroll
    for (int o = 1; o < 32; o <<= 1) {
        int y = __shfl_up_sync(0xffffffffu, x, o);
        if (lane >= o) x += y;
    }
    if (lane == 31) wsum[w] = x;
    __syncthreads();
    if (w == 0) {
        int s = wsum[lane];
        #pragma unroll
        for (int o = 1; o < 32; o <<= 1) {
            int y = __shfl_up_sync(0xffffffffu, s, o);
            if (lane >= o) s += y;
        }
        wsum[lane] = s;
    }
    __syncthreads();
    int off = g * EPG + (w ? wsum[w - 1] : 0) + x - v;   // exclusive
    g_off[i] = off;
    g_cursor[i] = off;
}

__global__ void k_fill(const int* __restrict__ esrc, const int* __restrict__ edst) {
    int e = blockIdx.x * 256 + threadIdx.x;
    if (e >= NEDGES) return;
    int s = esrc[e], d = edst[e];
    float nr = g_dinv[s] * g_dinv[d];
    int slot = atomicAdd(&g_cursor[d], 1);
    g_csrsrc[slot] = s;
    g_csrnrm[slot] = nr;
}

// ---------------- sparse aggregations (warp per node, unroll-4 batched MLP) ------
// WRITE_C: also emit c[n] = sum of incoming norms (replaces k_cvec).
template <bool WRITE_C>
__global__ __launch_bounds__(256) void k_agg64(const float* __restrict__ X,
                                               float* __restrict__ Y) {
    int node = blockIdx.x * 8 + (threadIdx.x >> 5);
    int lane = threadIdx.x & 31;
    const float2* xs = (const float2*)X;
    float dv = g_dinv[node];
    float2 xv = xs[node * 32 + lane];
    float2 acc;
    acc.x = dv * dv * xv.x;
    acc.y = dv * dv * xv.y;
    float csum = dv * dv;
    const int jb = g_off[node], je = jb + g_deg[node];
    int j = jb + ((je - jb) & 3);
    for (int jj = jb; jj < j; jj++) {
        int s = g_csrsrc[jj];
        float nr = g_csrnrm[jj];
        float2 v = xs[s * 32 + lane];
        acc.x += nr * v.x;
        acc.y += nr * v.y;
        if (WRITE_C) csum += nr;
    }
    for (; j < je; j += 4) {
        int s0 = g_csrsrc[j],     s1 = g_csrsrc[j + 1];
        int s2 = g_csrsrc[j + 2], s3 = g_csrsrc[j + 3];
        float n0 = g_csrnrm[j],     n1 = g_csrnrm[j + 1];
        float n2 = g_csrnrm[j + 2], n3 = g_csrnrm[j + 3];
        float2 v0 = xs[s0 * 32 + lane];
        float2 v1 = xs[s1 * 32 + lane];
        float2 v2 = xs[s2 * 32 + lane];
        float2 v3 = xs[s3 * 32 + lane];
        acc.x += n0 * v0.x; acc.y += n0 * v0.y;
        acc.x += n1 * v1.x; acc.y += n1 * v1.y;
        acc.x += n2 * v2.x; acc.y += n2 * v2.y;
        acc.x += n3 * v3.x; acc.y += n3 * v3.y;
        if (WRITE_C) csum += n0 + n1 + n2 + n3;
    }
    ((float2*)Y)[node * 32 + lane] = acc;
    if (WRITE_C && lane == 0) g_c[node] = csum;
}

__global__ __launch_bounds__(256) void k_agg128(const float* __restrict__ X,
                                                float* __restrict__ Y) {
    int node = blockIdx.x * 8 + (threadIdx.x >> 5);
    int lane = threadIdx.x & 31;
    const float4* xs = (const float4*)X;
    float dv = g_dinv[node];
    float4 xv = xs[node * 32 + lane];
    float4 acc;
    float sl = dv * dv;
    acc.x = sl * xv.x; acc.y = sl * xv.y; acc.z = sl * xv.z; acc.w = sl * xv.w;
    const int jb = g_off[node], je = jb + g_deg[node];
    int j = jb + ((je - jb) & 3);
    for (int jj = jb; jj < j; jj++) {
        int s = g_csrsrc[jj];
        float nr = g_csrnrm[jj];
        float4 v = xs[s * 32 + lane];
        acc.x += nr * v.x; acc.y += nr * v.y; acc.z += nr * v.z; acc.w += nr * v.w;
    }
    for (; j < je; j += 4) {
        int s0 = g_csrsrc[j],     s1 = g_csrsrc[j + 1];
        int s2 = g_csrsrc[j + 2], s3 = g_csrsrc[j + 3];
        float n0 = g_csrnrm[j],     n1 = g_csrnrm[j + 1];
        float n2 = g_csrnrm[j + 2], n3 = g_csrnrm[j + 3];
        float4 v0 = xs[s0 * 32 + lane];
        float4 v1 = xs[s1 * 32 + lane];
        float4 v2 = xs[s2 * 32 + lane];
        float4 v3 = xs[s3 * 32 + lane];
        acc.x += n0 * v0.x; acc.y += n0 * v0.y; acc.z += n0 * v0.z; acc.w += n0 * v0.w;
        acc.x += n1 * v1.x; acc.y += n1 * v1.y; acc.z += n1 * v1.z; acc.w += n1 * v1.w;
        acc.x += n2 * v2.x; acc.y += n2 * v2.y; acc.z += n2 * v2.z; acc.w += n2 * v2.w;
        acc.x += n3 * v3.x; acc.y += n3 * v3.y; acc.z += n3 * v3.z; acc.w += n3 * v3.w;
    }
    ((float4*)Y)[node * 32 + lane] = acc;
}

// ---------------- 3xTF32 mma.sync GEMM: per-block 128 rows x 128 cols --------------
// B is tf32-split ONCE at smem staging (sBh/sBl); mainloop B is pure LDS.
// MAXP: fold maxpool stage-1 into epilogue. ZOUT: skip Y store, emit z = h . W3.
template <int K, bool RELU, bool GLOB, bool MAXP, bool ZOUT>
__global__ __launch_bounds__(256) void k_mgemm(
    const float* __restrict__ A, const float* __restrict__ W,
    const float* __restrict__ bias, float* __restrict__ Y,
    const float* __restrict__ W3) {
    extern __shared__ float sm[];
    __shared__ int   smax[128];
    __shared__ float szp[128][8];
    const int PA = K + 4;
    float* sA  = sm;                      // 128 * PA (fp32)
    float* sBh = sm + 128 * PA;           // K * 136 (tf32 hi)
    float* sBl = sBh + K * 136;           // K * 136 (tf32 lo residual)
    const int tid = threadIdx.x;
    const int rbase = blockIdx.x * 128;

    if (MAXP && tid < 128) smax[tid] = 0;

    for (int i = tid; i < 128 * (K / 4); i += 256) {
        int row = i / (K / 4), c = i % (K / 4);
        float4 v = *(const float4*)&A[(size_t)(rbase + row) * K + c * 4];
        *(float4*)&sA[row * PA + c * 4] = v;
    }
    for (int i = tid; i < K * 128; i += 256) {
        int row = i >> 7, c = i & 127;
        uint32_t hi, lo;
        split_tf32(W[i], hi, lo);
        sBh[row * 136 + c] = __uint_as_float(hi);
        sBl[row * 136 + c] = __uint_as_float(lo);
    }
    __syncthreads();

    const int lane = tid & 31, wid = tid >> 5;
    const int gp = lane >> 2, tg = lane & 3;
    const int m0 = (wid & 3) * 32, n0 = (wid >> 2) * 64;

    float4 acc[2][8];
    #pragma unroll
    for (int mf = 0; mf < 2; mf++)
        #pragma unroll
        for (int f = 0; f < 8; f++) acc[mf][f] = make_float4(0.f, 0.f, 0.f, 0.f);

    for (int ks = 0; ks < K / 8; ks++) {
        const int kc = ks * 8;
        uint32_t ah[2][4], al[2][4];
        #pragma unroll
        for (int mf = 0; mf < 2; mf++) {
            int r0 = m0 + mf * 16 + gp;
            float x0 = sA[r0 * PA + kc + tg];
            float x1 = sA[(r0 + 8) * PA + kc + tg];
            float x2 = sA[r0 * PA + kc + tg + 4];
            float x3 = sA[(r0 + 8) * PA + kc + tg + 4];
            split_tf32(x0, ah[mf][0], al[mf][0]);
            split_tf32(x1, ah[mf][1], al[mf][1]);
            split_tf32(x2, ah[mf][2], al[mf][2]);
            split_tf32(x3, ah[mf][3], al[mf][3]);
        }
        #pragma unroll
        for (int f = 0; f < 8; f++) {
            int n = n0 + f * 8 + gp;
            uint32_t bh[2], bl[2];
            bh[0] = __float_as_uint(sBh[(kc + tg) * 136 + n]);
            bh[1] = __float_as_uint(sBh[(kc + tg + 4) * 136 + n]);
            bl[0] = __float_as_uint(sBl[(kc + tg) * 136 + n]);
            bl[1] = __float_as_uint(sBl[(kc + tg + 4) * 136 + n]);
            #pragma unroll
            for (int mf = 0; mf < 2; mf++) {
                mma_tf32(acc[mf][f], ah[mf], bh);
                mma_tf32(acc[mf][f], ah[mf], bl);
                mma_tf32(acc[mf][f], al[mf], bh);
            }
        }
    }

    float colmax[8][2];
    if (MAXP) {
        #pragma unroll
        for (int f = 0; f < 8; f++) { colmax[f][0] = 0.f; colmax[f][1] = 0.f; }
    }
    float zp[2][2] = {{0.f, 0.f}, {0.f, 0.f}};

    const float* gw = GLOB ? &g_gW[(rbase >> 10) * HID] : nullptr;
    #pragma unroll
    for (int mf = 0; mf < 2; mf++) {
        int r0 = rbase + m0 + mf * 16 + gp;
        int r1 = r0 + 8;
        float cc0 = GLOB ? g_c[r0] : 0.f;
        float cc1 = GLOB ? g_c[r1] : 0.f;
        #pragma unroll
        for (int f = 0; f < 8; f++) {
            int c = n0 + f * 8 + 2 * tg;
            float2 bv = *(const float2*)&bias[c];
            float4 a = acc[mf][f];
            float2 o0 = {a.x + bv.x, a.y + bv.y};
            float2 o1 = {a.z + bv.x, a.w + bv.y};
            if (GLOB) {
                float2 gv = *(const float2*)&gw[c];
                o0.x += cc0 * gv.x; o0.y += cc0 * gv.y;
                o1.x += cc1 * gv.x; o1.y += cc1 * gv.y;
            }
            if (RELU) {
                o0.x = fmaxf(o0.x, 0.f); o0.y = fmaxf(o0.y, 0.f);
                o1.x = fmaxf(o1.x, 0.f); o1.y = fmaxf(o1.y, 0.f);
            }
            if (!ZOUT) {
                *(float2*)&Y[(size_t)r0 * 128 + c] = o0;
                *(float2*)&Y[(size_t)r1 * 128 + c] = o1;
            }
            if (MAXP) {
                colmax[f][0] = fmaxf(colmax[f][0], fmaxf(o0.x, o1.x));
                colmax[f][1] = fmaxf(colmax[f][1], fmaxf(o0.y, o1.y));
            }
            if (ZOUT) {
                float w3a = W3[c], w3b = W3[c + 1];
                zp[mf][0] += o0.x * w3a + o0.y * w3b;
                zp[mf][1] += o1.x * w3a + o1.y * w3b;
            }
        }
    }

    if (MAXP) {
        #pragma unroll
        for (int f = 0; f < 8; f++) {
            int c = n0 + f * 8 + 2 * tg;
            atomicMax(&smax[c],     __float_as_int(colmax[f][0]));
            atomicMax(&smax[c + 1], __float_as_int(colmax[f][1]));
        }
        __syncthreads();
        if (tid < 128) g_mpp[(size_t)blockIdx.x * HID + tid] = __int_as_float(smax[tid]);
    }

    if (ZOUT) {
        int slot = ((wid >> 2) << 2) | tg;
        #pragma unroll
        for (int mf = 0; mf < 2; mf++) {
            szp[m0 + mf * 16 + gp][slot]     = zp[mf][0];
            szp[m0 + mf * 16 + gp + 8][slot] = zp[mf][1];
        }
        __syncthreads();
        if (tid < 128) {
            float z = 0.f;
            #pragma unroll
            for (int k = 0; k < 8; k++) z += szp[tid][k];
            g_z[rbase + tid] = z;
        }
    }
}

// ---------------- fused maxpool stage-2 + global path matmuls ----------------
__global__ void k_globs2(const float* __restrict__ Wf, const float* __restrict__ bf,
                         const float* __restrict__ W2) {
    __shared__ float s1[HID];
    __shared__ float s2[HID];
    int g = blockIdx.x, t = threadIdx.x;
    float m = -CUDART_INF_F;
    #pragma unroll
    for (int s = 0; s < 8; s++) m = fmaxf(m, g_mpp[(g * 8 + s) * HID + t]);
    s1[t] = m;
    __syncthreads();
    float acc = bf[t];
    for (int k = 0; k < HID; k++) acc += s1[k] * Wf[k * HID + t];
    s2[t] = acc;
    __syncthreads();
    float a2 = 0.f;
    for (int k = 0; k < HID; k++) a2 += s2[k] * W2[(HID + k) * HID + t];
    g_gW[g * HID + t] = a2;
}

// ---------------- fused logit + per-graph top-K mask ----------------
__global__ __launch_bounds__(256) void k_logitk(const float* __restrict__ b3,
                                                float* __restrict__ out) {
    __shared__ float sz[NPER];
    __shared__ float slog[NPER];
    __shared__ float v[NPER];
    __shared__ float wmax[8];
    __shared__ float sth;
    __shared__ int sidx;
    const int g = blockIdx.x, t = threadIdx.x;
    const int lane = t & 31, warp = t >> 5;
    const float bb = b3[0];

    for (int i = t; i < NPER; i += 256) sz[i] = g_z[g * NPER + i];
    __syncthreads();

    for (int ln = warp; ln < NPER; ln += 8) {
        int node = g * NPER + ln;
        int jb = g_off[node], dg = g_deg[node];
        float part = 0.f;
        for (int j = lane; j < dg; j += 32)
            part += g_csrnrm[jb + j] * sz[g_csrsrc[jb + j] & (NPER - 1)];
        #pragma unroll
        for (int o = 16; o; o >>= 1) part += __shfl_xor_sync(0xffffffffu, part, o);
        if (lane == 0) {
            float dv = g_dinv[node];
            float lv = part + dv * dv * sz[ln] + bb;
            slog[ln] = lv;
            v[ln] = lv;
        }
    }
    __syncthreads();

    for (int it = 0; it < TOPK; it++) {
        float m = -CUDART_INF_F;
        for (int i = t; i < NPER; i += 256) m = fmaxf(m, v[i]);
        #pragma unroll
        for (int o = 16; o; o >>= 1) m = fmaxf(m, __shfl_xor_sync(0xffffffffu, m, o));
        if (lane == 0) wmax[warp] = m;
        __syncthreads();
        if (t == 0) {
            float mm = wmax[0];
            #pragma unroll
            for (int w = 1; w < 8; w++) mm = fmaxf(mm, wmax[w]);
            sth = mm;
            sidx = 0x7fffffff;
        }
        __syncthreads();
        float mm = sth;
        for (int i = t; i < NPER; i += 256)
            if (v[i] == mm) atomicMin(&sidx, i);
        __syncthreads();
        if (t == 0) v[sidx] = -CUDART_INF_F;
        __syncthreads();
    }
    float th = sth;
    for (int i = t; i < NPER; i += 256)
        out[g * NPER + i] = (slog[i] >= th) ? 1.0f : 0.0f;
}

// ---------------- host launcher ----------------
extern "C" void kernel_launch(void* const* d_in, const int* in_sizes, int n_in,
                              void* d_out, int out_size) {
    const float* x    = (const float*)d_in[0];
    const int*   esrc = (const int*)d_in[1];
    const int*   edst = (const int*)d_in[2];
    const float* W0 = (const float*)d_in[4];
    const float* b0 = (const float*)d_in[5];
    const float* W1 = (const float*)d_in[6];
    const float* b1 = (const float*)d_in[7];
    const float* Wf = (const float*)d_in[8];
    const float* bf = (const float*)d_in[9];
    const float* W2 = (const float*)d_in[10];
    const float* b2 = (const float*)d_in[11];
    const float* W3 = (const float*)d_in[12];
    const float* b3 = (const float*)d_in[13];
    float* out = (float*)d_out;

    float *T0, *T1;
    int* degp;
    cudaGetSymbolAddress((void**)&T0, g_T0);
    cudaGetSymbolAddress((void**)&T1, g_T1);
    cudaGetSymbolAddress((void**)&degp, g_deg);

    const int SM64  = (128 * 68  + 2 * 64  * 136) * 4;   // 104448
    const int SM128 = (128 * 132 + 2 * 128 * 136) * 4;   // 206848
    cudaFuncSetAttribute(k_mgemm<64, true, false, true, false>,
                         cudaFuncAttributeMaxDynamicSharedMemorySize, SM64);
    cudaFuncSetAttribute(k_mgemm<128, true, false, false, false>,
                         cudaFuncAttributeMaxDynamicSharedMemorySize, SM128);
    cudaFuncSetAttribute(k_mgemm<128, true, true, false, true>,
                         cudaFuncAttributeMaxDynamicSharedMemorySize, SM128);

    // --- CSR + norms (hist -> fused per-graph scan -> fill) ---
    cudaMemsetAsync(degp, 0, NNODES * sizeof(int));
    k_hist<<<NEDGES / 256, 256>>>(edst);
    k_scan<<<NGRAPH, 1024>>>();
    k_fill<<<NEDGES / 256, 256>>>(esrc, edst);

    // --- conv0: h0 = relu(agg(x) @ W0 + b0); epilogue emits maxpool partials ---
    k_agg64<true><<<NNODES / 8, 256>>>(x, T1);
    k_mgemm<64, true, false, true, false><<<NNODES / 128, 256, SM64>>>(T1, W0, b0, T0, nullptr);

    // --- global path: mp2 + (mp @ Wf + bf) @ W2_bottom ---
    k_globs2<<<NGRAPH, HID>>>(Wf, bf, W2);

    // --- conv1 (applied twice with same weights) ---
    k_agg128<<<NNODES / 8, 256>>>(T0, T1);
    k_mgemm<128, true, false, false, false><<<NNODES / 128, 256, SM128>>>(T1, W1, b1, T0, nullptr);
    k_agg128<<<NNODES / 8, 256>>>(T0, T1);
    k_mgemm<128, true, false, false, false><<<NNODES / 128, 256, SM128>>>(T1, W1, b1, T0, nullptr);

    // --- conv2 + conv3 projection fused: epilogue computes z = h . W3, no h store ---
    k_agg128<<<NNODES / 8, 256>>>(T0, T1);
    k_mgemm<128, true, true, false, true><<<NNODES / 128, 256, SM128>>>(T1, W2, b2, nullptr, W3);

    // --- fused logit + per-graph top-10 mask ---
    k_logitk<<<NGRAPH, 256>>>(b3, out);
}